// round 2
// baseline (speedup 1.0000x reference)
#include <cuda_runtime.h>
#include <math.h>

#define NN 50000
#define EE 500000
#define HH 128
#define H2 256
#define GG 64
#define LL 4

// ---------------- device scratch (no allocations allowed) ----------------
static __device__ int   g_cnt[NN];
static __device__ int   g_fill[NN];
static __device__ int   g_rowptr[NN + 1];
static __device__ int   g_eid[EE];
static __device__ int   g_csrc[EE];
static __device__ float g_cea[EE];
static __device__ float g_xs[NN * HH];
static __device__ float g_xd[NN * HH];
static __device__ float g_o[NN * HH];
static __device__ float g_h[NN * HH];
static __device__ float g_r[NN * HH];
static __device__ float g_hmid[NN * H2];
static __device__ int   g_gstart[GG + 1];
static __device__ float g_pool[GG * HH];

// ---------------- CSR construction (deterministic via eid sort) ----------------
__global__ void zero_k(int N) {
    int i = blockIdx.x * blockDim.x + threadIdx.x;
    if (i < N) { g_cnt[i] = 0; g_fill[i] = 0; }
}

__global__ void count_k(const int* __restrict__ ei, int E) {
    int i = blockIdx.x * blockDim.x + threadIdx.x;
    if (i < E) atomicAdd(&g_cnt[ei[E + i]], 1);
}

__global__ void scan_k(int n) {
    __shared__ int sums[1024];
    int t = threadIdx.x;
    int per = (n + 1023) >> 10;
    int base = t * per;
    int s = 0;
    for (int i = 0; i < per; i++) { int idx = base + i; if (idx < n) s += g_cnt[idx]; }
    sums[t] = s;
    __syncthreads();
    for (int off = 1; off < 1024; off <<= 1) {
        int v = (t >= off) ? sums[t - off] : 0;
        __syncthreads();
        sums[t] += v;
        __syncthreads();
    }
    int run = (t == 0) ? 0 : sums[t - 1];
    for (int i = 0; i < per; i++) {
        int idx = base + i;
        if (idx < n) { g_rowptr[idx] = run; run += g_cnt[idx]; }
    }
    if (t == 0) g_rowptr[n] = sums[1023];
}

__global__ void scatter_k(const int* __restrict__ ei, int E) {
    int i = blockIdx.x * blockDim.x + threadIdx.x;
    if (i >= E) return;
    int dst = ei[E + i];
    int p = atomicAdd(&g_fill[dst], 1);
    g_eid[g_rowptr[dst] + p] = i;
}

// sort each node's edge list by edge id (deterministic order), then fill src/attr
__global__ void sortfill_k(const int* __restrict__ ei, const float* __restrict__ ea, int N) {
    int n = blockIdx.x * blockDim.x + threadIdx.x;
    if (n >= N) return;
    int s = g_rowptr[n], e = g_rowptr[n + 1];
    for (int i = s + 1; i < e; i++) {
        int v = g_eid[i];
        int j = i - 1;
        while (j >= s && g_eid[j] > v) { g_eid[j + 1] = g_eid[j]; j--; }
        g_eid[j + 1] = v;
    }
    for (int i = s; i < e; i++) {
        int id = g_eid[i];
        g_csrc[i] = ei[id];
        g_cea[i] = ea[id];
    }
}

// ---------------- fused SGEMM: C = epilogue(A[MxK] @ W[KxNout]) ----------------
// double-buffered smem pipeline; epilogue: +bias -> (BN) -> (ReLU) -> (+addsrc)
// -> store C -> optionally also rout = ReLU(BN2(C_val))
__global__ void __launch_bounds__(256) sgemm(
    const float* __restrict__ A, const float* __restrict__ W,
    const float* __restrict__ bias, float* C,
    int M, int K, int Nout,
    const float* __restrict__ bng, const float* __restrict__ bnb,
    const float* __restrict__ bnm, const float* __restrict__ bnv,
    int do_relu, const float* addsrc,
    float* __restrict__ rout,
    const float* __restrict__ rg, const float* __restrict__ rb2,
    const float* __restrict__ rm, const float* __restrict__ rv)
{
    __shared__ float As[2][8][128];
    __shared__ float Ws[2][8][128];
    const int tid = threadIdx.x;
    const int m0 = blockIdx.x * 128;
    const int n0 = blockIdx.y * 128;
    const int tx = tid & 15;
    const int ty = tid >> 4;
    const int ar = tid >> 1;
    const int ac = (tid & 1) << 2;
    const int wr = tid >> 5;
    const int wc = (tid & 31) << 2;

    float acc[8][8];
#pragma unroll
    for (int i = 0; i < 8; i++)
#pragma unroll
        for (int j = 0; j < 8; j++) acc[i][j] = 0.f;

    const bool arow_ok = (m0 + ar) < M;
    const float* Aptr = A + (size_t)(m0 + ar) * K + ac;
    const float* Wptr = W + (size_t)wr * Nout + n0 + wc;

    // prologue: load k-tile 0 into buffer 0
    float4 av = make_float4(0.f, 0.f, 0.f, 0.f);
    if (arow_ok) av = *reinterpret_cast<const float4*>(Aptr);
    float4 wv = *reinterpret_cast<const float4*>(Wptr);
    As[0][ac + 0][ar] = av.x; As[0][ac + 1][ar] = av.y;
    As[0][ac + 2][ar] = av.z; As[0][ac + 3][ar] = av.w;
    *reinterpret_cast<float4*>(&Ws[0][wr][wc]) = wv;
    __syncthreads();

    int cur = 0;
    for (int k0 = 0; k0 < K; k0 += 8) {
        const bool has_next = (k0 + 8) < K;
        float4 nav = make_float4(0.f, 0.f, 0.f, 0.f);
        float4 nwv = make_float4(0.f, 0.f, 0.f, 0.f);
        if (has_next) {
            if (arow_ok) nav = *reinterpret_cast<const float4*>(Aptr + k0 + 8);
            nwv = *reinterpret_cast<const float4*>(Wptr + (size_t)(k0 + 8) * Nout);
        }
#pragma unroll
        for (int kk = 0; kk < 8; kk++) {
            float4 a0 = *reinterpret_cast<const float4*>(&As[cur][kk][ty * 8]);
            float4 a1 = *reinterpret_cast<const float4*>(&As[cur][kk][ty * 8 + 4]);
            float4 b0 = *reinterpret_cast<const float4*>(&Ws[cur][kk][tx * 8]);
            float4 b1 = *reinterpret_cast<const float4*>(&Ws[cur][kk][tx * 8 + 4]);
            float ra[8] = {a0.x, a0.y, a0.z, a0.w, a1.x, a1.y, a1.z, a1.w};
            float rbv[8] = {b0.x, b0.y, b0.z, b0.w, b1.x, b1.y, b1.z, b1.w};
#pragma unroll
            for (int i = 0; i < 8; i++)
#pragma unroll
                for (int j = 0; j < 8; j++)
                    acc[i][j] = fmaf(ra[i], rbv[j], acc[i][j]);
        }
        if (has_next) {
            int nxt = cur ^ 1;
            As[nxt][ac + 0][ar] = nav.x; As[nxt][ac + 1][ar] = nav.y;
            As[nxt][ac + 2][ar] = nav.z; As[nxt][ac + 3][ar] = nav.w;
            *reinterpret_cast<float4*>(&Ws[nxt][wr][wc]) = nwv;
            __syncthreads();
            cur = nxt;
        }
    }

#pragma unroll
    for (int i = 0; i < 8; i++) {
        int row = m0 + ty * 8 + i;
        if (row >= M) continue;
#pragma unroll
        for (int j = 0; j < 8; j++) {
            int col = n0 + tx * 8 + j;
            float v = acc[i][j] + bias[col];
            if (bng) v = fmaf(bng[col] * (v - bnm[col]), rsqrtf(bnv[col] + 1e-5f), bnb[col]);
            if (do_relu) v = fmaxf(v, 0.f);
            if (addsrc) v += addsrc[(size_t)row * Nout + col];
            C[(size_t)row * Nout + col] = v;
            if (rout) {
                float r = fmaf(rg[col] * (v - rm[col]), rsqrtf(rv[col] + 1e-5f), rb2[col]);
                rout[(size_t)row * Nout + col] = fmaxf(r, 0.f);
            }
        }
    }
}

// ---------------- GENConv softmax aggregation: one warp per node ----------------
__device__ __forceinline__ void softmax_upd(float xv, float e, float tl,
                                            float& m, float& den, float& num)
{
    float msg = fmaxf(xv + e, 0.f) + 1e-7f;
    float z = msg * tl;
    if (z <= m) {
        float w = __expf(z - m);
        den += w;
        num = fmaf(msg, w, num);
    } else {
        float w = __expf(m - z);
        den = fmaf(den, w, 1.f);
        num = fmaf(num, w, msg);
        m = z;
    }
}

__global__ void __launch_bounds__(256) agg_kernel(
    const float* __restrict__ xs, const float* __restrict__ xd,
    float* __restrict__ outp,
    const float* __restrict__ ew, const float* __restrict__ ebias,
    const float* __restrict__ tptr, int N)
{
    int gw = (blockIdx.x * blockDim.x + threadIdx.x) >> 5;
    int lane = threadIdx.x & 31;
    if (gw >= N) return;
    int row = g_rowptr[gw];
    int deg = g_rowptr[gw + 1] - row;
    float tl = tptr[0];
    float4 ew4 = *reinterpret_cast<const float4*>(ew + lane * 4);
    float4 eb4 = *reinterpret_cast<const float4*>(ebias + lane * 4);
    float m0 = -1e30f, m1 = -1e30f, m2 = -1e30f, m3 = -1e30f;
    float d0 = 0.f, d1 = 0.f, d2 = 0.f, d3 = 0.f;
    float s0 = 0.f, s1 = 0.f, s2 = 0.f, s3 = 0.f;
    for (int j = 0; j < deg; j++) {
        int s = g_csrc[row + j];
        float a = g_cea[row + j];
        float4 xv = *reinterpret_cast<const float4*>(xs + (size_t)s * HH + lane * 4);
        softmax_upd(xv.x, fmaf(a, ew4.x, eb4.x), tl, m0, d0, s0);
        softmax_upd(xv.y, fmaf(a, ew4.y, eb4.y), tl, m1, d1, s1);
        softmax_upd(xv.z, fmaf(a, ew4.z, eb4.z), tl, m2, d2, s2);
        softmax_upd(xv.w, fmaf(a, ew4.w, eb4.w), tl, m3, d3, s3);
    }
    float4 xdv = *reinterpret_cast<const float4*>(xd + (size_t)gw * HH + lane * 4);
    float4 o;
    o.x = s0 / fmaxf(d0, 1e-16f) + xdv.x;
    o.y = s1 / fmaxf(d1, 1e-16f) + xdv.y;
    o.z = s2 / fmaxf(d2, 1e-16f) + xdv.z;
    o.w = s3 / fmaxf(d3, 1e-16f) + xdv.w;
    *reinterpret_cast<float4*>(outp + (size_t)gw * HH + lane * 4) = o;
}

// ---------------- pooling + classifier ----------------
__global__ void gstart_k(const int* __restrict__ batch, int N, int G) {
    int g = threadIdx.x;
    if (g > G) return;
    int lo = 0, hi = N;
    while (lo < hi) { int mid = (lo + hi) >> 1; if (batch[mid] < g) lo = mid + 1; else hi = mid; }
    g_gstart[g] = lo;
}

__global__ void pool_k(const float* __restrict__ hfin) {
    int g = blockIdx.x, c = threadIdx.x;
    int s = g_gstart[g], e = g_gstart[g + 1];
    float acc = 0.f;
    for (int i = s; i < e; i++) acc += hfin[(size_t)i * HH + c];
    g_pool[g * HH + c] = acc / fmaxf((float)(e - s), 1.f);
}

__global__ void cls_k(const float* __restrict__ clin, const float* __restrict__ cw,
                      const float* __restrict__ cb, float* __restrict__ out, int G) {
    int t = blockIdx.x * blockDim.x + threadIdx.x;
    if (t >= G * 2) return;
    int g = t >> 1, c = t & 1;
    float acc = cb[c];
    for (int i = 0; i < HH; i++) acc = fmaf(g_pool[g * HH + i], cw[i * 2 + c], acc);
    for (int k = 0; k < 8; k++) acc = fmaf(clin[g * 8 + k], cw[(HH + k) * 2 + c], acc);
    out[t] = acc;
}

// ---------------- launch ----------------
extern "C" void kernel_launch(void* const* d_in, const int* in_sizes, int n_in,
                              void* d_out, int out_size)
{
    const float* x        = (const float*)d_in[0];
    const int*   ei       = (const int*)  d_in[1];
    const float* eattr    = (const float*)d_in[2];
    const int*   batch    = (const int*)  d_in[3];
    const float* clinical = (const float*)d_in[4];
    const float* lsw      = (const float*)d_in[5];
    const float* lsb      = (const float*)d_in[6];
    const float* ldw      = (const float*)d_in[7];
    const float* ldb      = (const float*)d_in[8];
    const float* ew       = (const float*)d_in[9];
    const float* eb       = (const float*)d_in[10];
    const float* t        = (const float*)d_in[11];
    const float* w1       = (const float*)d_in[12];
    const float* b1       = (const float*)d_in[13];
    const float* bng      = (const float*)d_in[14];
    const float* bnb      = (const float*)d_in[15];
    const float* bnm      = (const float*)d_in[16];
    const float* bnv      = (const float*)d_in[17];
    const float* w2       = (const float*)d_in[18];
    const float* b2       = (const float*)d_in[19];
    const float* ng       = (const float*)d_in[20];
    const float* nb       = (const float*)d_in[21];
    const float* nm       = (const float*)d_in[22];
    const float* nv       = (const float*)d_in[23];
    const float* cw       = (const float*)d_in[24];
    const float* cb       = (const float*)d_in[25];
    float* out = (float*)d_out;

    int N = in_sizes[0] / 256;
    int E = in_sizes[1] / 2;
    int G = in_sizes[4] / 8;

    float *p_xs, *p_xd, *p_o, *p_h, *p_r, *p_hmid;
    cudaGetSymbolAddress((void**)&p_xs, g_xs);
    cudaGetSymbolAddress((void**)&p_xd, g_xd);
    cudaGetSymbolAddress((void**)&p_o, g_o);
    cudaGetSymbolAddress((void**)&p_h, g_h);
    cudaGetSymbolAddress((void**)&p_r, g_r);
    cudaGetSymbolAddress((void**)&p_hmid, g_hmid);

    const int thr = 256;
    zero_k<<<(N + thr - 1) / thr, thr>>>(N);
    count_k<<<(E + thr - 1) / thr, thr>>>(ei, E);
    scan_k<<<1, 1024>>>(N);
    scatter_k<<<(E + thr - 1) / thr, thr>>>(ei, E);
    sortfill_k<<<(N + thr - 1) / thr, thr>>>(ei, eattr, N);

    int gmx = (N + 127) / 128;

    // input projections: xs0 = x@Wsrc+b, xd0 = x@Wdst+b
    sgemm<<<dim3(gmx, 1), thr>>>(x, lsw, lsb, p_xs, N, 256, 128,
        nullptr, nullptr, nullptr, nullptr, 0, nullptr,
        nullptr, nullptr, nullptr, nullptr, nullptr);
    sgemm<<<dim3(gmx, 1), thr>>>(x, ldw, ldb, p_xd, N, 256, 128,
        nullptr, nullptr, nullptr, nullptr, 0, nullptr,
        nullptr, nullptr, nullptr, nullptr, nullptr);

    for (int l = 0; l < LL; l++) {
        const float* xsl = l ? p_r : p_xs;
        const float* xdl = l ? p_r : p_xd;
        agg_kernel<<<(N + 7) / 8, thr>>>(xsl, xdl, p_o,
                                         ew + l * HH, eb + l * HH, t + l, N);
        // GEMM1: out @ W1 + b1 -> BN -> ReLU  => hmid [N, 256]
        sgemm<<<dim3(gmx, 2), thr>>>(p_o, w1 + (size_t)l * HH * H2, b1 + l * H2, p_hmid,
            N, HH, H2,
            bng + l * H2, bnb + l * H2, bnm + l * H2, bnv + l * H2, 1, nullptr,
            nullptr, nullptr, nullptr, nullptr, nullptr);
        // GEMM2: hmid @ W2 + b2 (+h residual for l>0) => h; also r = ReLU(BN_norm[(l+1)%4](h))
        int nl = (l + 1) & 3;
        sgemm<<<dim3(gmx, 1), thr>>>(p_hmid, w2 + (size_t)l * H2 * HH, b2 + l * HH, p_h,
            N, H2, HH,
            nullptr, nullptr, nullptr, nullptr, 0, l ? p_h : nullptr,
            p_r, ng + nl * HH, nb + nl * HH, nm + nl * HH, nv + nl * HH);
    }

    // after layer 3, p_r holds relu(bn(h, norm[0])) = hfin
    gstart_k<<<1, 128>>>(batch, N, G);
    pool_k<<<G, 128>>>(p_r);
    cls_k<<<1, 128>>>(clinical, cw, cb, out, G);
}

// round 16
// speedup vs baseline: 1.0368x; 1.0368x over previous
#include <cuda_runtime.h>
#include <math.h>

#define NN 50000
#define EE 500000
#define HH 128
#define H2 256
#define GG 64
#define LL 4

// ---------------- device scratch (no allocations allowed) ----------------
static __device__ int   g_cnt[NN];
static __device__ int   g_fill[NN];
static __device__ int   g_rowptr[NN + 1];
static __device__ int   g_eid[EE];
static __device__ int   g_csrc[EE];
static __device__ float g_cea[EE];
static __device__ float g_xs[NN * HH];
static __device__ float g_xd[NN * HH];
static __device__ float g_o[NN * HH];
static __device__ float g_h[NN * HH];
static __device__ float g_r[NN * HH];
static __device__ float g_hmid[NN * H2];
static __device__ int   g_gstart[GG + 1];
static __device__ float g_pool[GG * HH];

// ---------------- packed f32x2 helpers (Blackwell FFMA2 path) ----------------
__device__ __forceinline__ void fma2(unsigned long long& d, unsigned long long a,
                                     unsigned long long b) {
    asm("fma.rn.f32x2 %0, %1, %2, %0;" : "+l"(d) : "l"(a), "l"(b));
}
__device__ __forceinline__ unsigned long long dup2(float a) {
    unsigned long long r;
    asm("mov.b64 %0, {%1, %1};" : "=l"(r) : "f"(a));
    return r;
}
__device__ __forceinline__ void unpack2(unsigned long long v, float& lo, float& hi) {
    asm("mov.b64 {%0, %1}, %2;" : "=f"(lo), "=f"(hi) : "l"(v));
}

// ---------------- CSR construction (deterministic via eid sort) ----------------
__global__ void zero_k(int N) {
    int i = blockIdx.x * blockDim.x + threadIdx.x;
    if (i < N) { g_cnt[i] = 0; g_fill[i] = 0; }
}

__global__ void count_k(const int* __restrict__ ei, int E) {
    int i = blockIdx.x * blockDim.x + threadIdx.x;
    if (i < E) atomicAdd(&g_cnt[ei[E + i]], 1);
}

__global__ void scan_k(int n) {
    __shared__ int sums[1024];
    int t = threadIdx.x;
    int per = (n + 1023) >> 10;
    int base = t * per;
    int s = 0;
    for (int i = 0; i < per; i++) { int idx = base + i; if (idx < n) s += g_cnt[idx]; }
    sums[t] = s;
    __syncthreads();
    for (int off = 1; off < 1024; off <<= 1) {
        int v = (t >= off) ? sums[t - off] : 0;
        __syncthreads();
        sums[t] += v;
        __syncthreads();
    }
    int run = (t == 0) ? 0 : sums[t - 1];
    for (int i = 0; i < per; i++) {
        int idx = base + i;
        if (idx < n) { g_rowptr[idx] = run; run += g_cnt[idx]; }
    }
    if (t == 0) g_rowptr[n] = sums[1023];
}

__global__ void scatter_k(const int* __restrict__ ei, int E) {
    int i = blockIdx.x * blockDim.x + threadIdx.x;
    if (i >= E) return;
    int dst = ei[E + i];
    int p = atomicAdd(&g_fill[dst], 1);
    g_eid[g_rowptr[dst] + p] = i;
}

// sort each node's edge list by edge id (deterministic order), then fill src/attr
__global__ void sortfill_k(const int* __restrict__ ei, const float* __restrict__ ea, int N) {
    int n = blockIdx.x * blockDim.x + threadIdx.x;
    if (n >= N) return;
    int s = g_rowptr[n], e = g_rowptr[n + 1];
    for (int i = s + 1; i < e; i++) {
        int v = g_eid[i];
        int j = i - 1;
        while (j >= s && g_eid[j] > v) { g_eid[j + 1] = g_eid[j]; j--; }
        g_eid[j + 1] = v;
    }
    for (int i = s; i < e; i++) {
        int id = g_eid[i];
        g_csrc[i] = ei[id];
        g_cea[i] = ea[id];
    }
}

// ---------------- fused SGEMM: C = epilogue(A[MxK] @ W[KxNout]) ----------------
// double-buffered smem pipeline, packed f32x2 FFMA2 inner loop.
// epilogue: +bias -> (BN) -> (ReLU) -> (+addsrc) -> store C
//           -> optionally also rout = ReLU(BN2(C_val))
__global__ void __launch_bounds__(256) sgemm(
    const float* __restrict__ A, const float* __restrict__ W,
    const float* __restrict__ bias, float* C,
    int M, int K, int Nout,
    const float* __restrict__ bng, const float* __restrict__ bnb,
    const float* __restrict__ bnm, const float* __restrict__ bnv,
    int do_relu, const float* addsrc,
    float* __restrict__ rout,
    const float* __restrict__ rg, const float* __restrict__ rb2,
    const float* __restrict__ rm, const float* __restrict__ rv)
{
    __shared__ float As[2][8][128];
    __shared__ float Ws[2][8][128];
    const int tid = threadIdx.x;
    const int m0 = blockIdx.x * 128;
    const int n0 = blockIdx.y * 128;
    const int tx = tid & 15;
    const int ty = tid >> 4;
    const int ar = tid >> 1;
    const int ac = (tid & 1) << 2;
    const int wr = tid >> 5;
    const int wc = (tid & 31) << 4;   // byte-level: 4 floats

    // packed accumulators: acc2[i][jp] holds cols (2jp, 2jp+1) for row i
    unsigned long long acc2[8][4];
    const unsigned long long zz = dup2(0.f);
#pragma unroll
    for (int i = 0; i < 8; i++)
#pragma unroll
        for (int j = 0; j < 4; j++) acc2[i][j] = zz;

    const bool arow_ok = (m0 + ar) < M;
    const float* Aptr = A + (size_t)(m0 + ar) * K + ac;
    const float* Wptr = W + (size_t)wr * Nout + n0 + ((tid & 31) << 2);

    // prologue: load k-tile 0 into buffer 0
    float4 av = make_float4(0.f, 0.f, 0.f, 0.f);
    if (arow_ok) av = *reinterpret_cast<const float4*>(Aptr);
    float4 wv = *reinterpret_cast<const float4*>(Wptr);
    As[0][ac + 0][ar] = av.x; As[0][ac + 1][ar] = av.y;
    As[0][ac + 2][ar] = av.z; As[0][ac + 3][ar] = av.w;
    *reinterpret_cast<float4*>(reinterpret_cast<char*>(&Ws[0][wr][0]) + wc) = wv;
    __syncthreads();

    int cur = 0;
    for (int k0 = 0; k0 < K; k0 += 8) {
        const bool has_next = (k0 + 8) < K;
        float4 nav = make_float4(0.f, 0.f, 0.f, 0.f);
        float4 nwv = make_float4(0.f, 0.f, 0.f, 0.f);
        if (has_next) {
            if (arow_ok) nav = *reinterpret_cast<const float4*>(Aptr + k0 + 8);
            nwv = *reinterpret_cast<const float4*>(Wptr + (size_t)(k0 + 8) * Nout);
        }
#pragma unroll
        for (int kk = 0; kk < 8; kk++) {
            float4 a0 = *reinterpret_cast<const float4*>(&As[cur][kk][ty * 8]);
            float4 a1 = *reinterpret_cast<const float4*>(&As[cur][kk][ty * 8 + 4]);
            ulonglong2 b01 = *reinterpret_cast<const ulonglong2*>(&Ws[cur][kk][tx * 8]);
            ulonglong2 b23 = *reinterpret_cast<const ulonglong2*>(&Ws[cur][kk][tx * 8 + 4]);
            float ra[8] = {a0.x, a0.y, a0.z, a0.w, a1.x, a1.y, a1.z, a1.w};
#pragma unroll
            for (int i = 0; i < 8; i++) {
                unsigned long long ad = dup2(ra[i]);
                fma2(acc2[i][0], ad, b01.x);
                fma2(acc2[i][1], ad, b01.y);
                fma2(acc2[i][2], ad, b23.x);
                fma2(acc2[i][3], ad, b23.y);
            }
        }
        if (has_next) {
            int nxt = cur ^ 1;
            As[nxt][ac + 0][ar] = nav.x; As[nxt][ac + 1][ar] = nav.y;
            As[nxt][ac + 2][ar] = nav.z; As[nxt][ac + 3][ar] = nav.w;
            *reinterpret_cast<float4*>(reinterpret_cast<char*>(&Ws[nxt][wr][0]) + wc) = nwv;
            __syncthreads();
            cur = nxt;
        }
    }

#pragma unroll
    for (int i = 0; i < 8; i++) {
        int row = m0 + ty * 8 + i;
        if (row >= M) continue;
#pragma unroll
        for (int jp = 0; jp < 4; jp++) {
            float v2[2];
            unpack2(acc2[i][jp], v2[0], v2[1]);
#pragma unroll
            for (int u = 0; u < 2; u++) {
                int col = n0 + tx * 8 + jp * 2 + u;
                float v = v2[u] + bias[col];
                if (bng) v = fmaf(bng[col] * (v - bnm[col]), rsqrtf(bnv[col] + 1e-5f), bnb[col]);
                if (do_relu) v = fmaxf(v, 0.f);
                if (addsrc) v += addsrc[(size_t)row * Nout + col];
                C[(size_t)row * Nout + col] = v;
                if (rout) {
                    float r = fmaf(rg[col] * (v - rm[col]), rsqrtf(rv[col] + 1e-5f), rb2[col]);
                    rout[(size_t)row * Nout + col] = fmaxf(r, 0.f);
                }
            }
        }
    }
}

// ---------------- GENConv softmax aggregation: one warp per node ----------------
__device__ __forceinline__ void softmax_upd(float xv, float e, float tl,
                                            float& m, float& den, float& num)
{
    float msg = fmaxf(xv + e, 0.f) + 1e-7f;
    float z = msg * tl;
    if (z <= m) {
        float w = __expf(z - m);
        den += w;
        num = fmaf(msg, w, num);
    } else {
        float w = __expf(m - z);
        den = fmaf(den, w, 1.f);
        num = fmaf(num, w, msg);
        m = z;
    }
}

__global__ void __launch_bounds__(256) agg_kernel(
    const float* __restrict__ xs, const float* __restrict__ xd,
    float* __restrict__ outp,
    const float* __restrict__ ew, const float* __restrict__ ebias,
    const float* __restrict__ tptr, int N)
{
    int gw = (blockIdx.x * blockDim.x + threadIdx.x) >> 5;
    int lane = threadIdx.x & 31;
    if (gw >= N) return;
    int row = g_rowptr[gw];
    int deg = g_rowptr[gw + 1] - row;
    float tl = tptr[0];
    float4 ew4 = *reinterpret_cast<const float4*>(ew + lane * 4);
    float4 eb4 = *reinterpret_cast<const float4*>(ebias + lane * 4);
    float m0 = -1e30f, m1 = -1e30f, m2 = -1e30f, m3 = -1e30f;
    float d0 = 0.f, d1 = 0.f, d2 = 0.f, d3 = 0.f;
    float s0 = 0.f, s1 = 0.f, s2 = 0.f, s3 = 0.f;
    for (int j = 0; j < deg; j++) {
        int s = g_csrc[row + j];
        float a = g_cea[row + j];
        float4 xv = *reinterpret_cast<const float4*>(xs + (size_t)s * HH + lane * 4);
        softmax_upd(xv.x, fmaf(a, ew4.x, eb4.x), tl, m0, d0, s0);
        softmax_upd(xv.y, fmaf(a, ew4.y, eb4.y), tl, m1, d1, s1);
        softmax_upd(xv.z, fmaf(a, ew4.z, eb4.z), tl, m2, d2, s2);
        softmax_upd(xv.w, fmaf(a, ew4.w, eb4.w), tl, m3, d3, s3);
    }
    float4 xdv = *reinterpret_cast<const float4*>(xd + (size_t)gw * HH + lane * 4);
    float4 o;
    o.x = s0 / fmaxf(d0, 1e-16f) + xdv.x;
    o.y = s1 / fmaxf(d1, 1e-16f) + xdv.y;
    o.z = s2 / fmaxf(d2, 1e-16f) + xdv.z;
    o.w = s3 / fmaxf(d3, 1e-16f) + xdv.w;
    *reinterpret_cast<float4*>(outp + (size_t)gw * HH + lane * 4) = o;
}

// ---------------- pooling + classifier ----------------
__global__ void gstart_k(const int* __restrict__ batch, int N, int G) {
    int g = threadIdx.x;
    if (g > G) return;
    int lo = 0, hi = N;
    while (lo < hi) { int mid = (lo + hi) >> 1; if (batch[mid] < g) lo = mid + 1; else hi = mid; }
    g_gstart[g] = lo;
}

__global__ void pool_k(const float* __restrict__ hfin) {
    int g = blockIdx.x, c = threadIdx.x;
    int s = g_gstart[g], e = g_gstart[g + 1];
    float acc = 0.f;
    for (int i = s; i < e; i++) acc += hfin[(size_t)i * HH + c];
    g_pool[g * HH + c] = acc / fmaxf((float)(e - s), 1.f);
}

__global__ void cls_k(const float* __restrict__ clin, const float* __restrict__ cw,
                      const float* __restrict__ cb, float* __restrict__ out, int G) {
    int t = blockIdx.x * blockDim.x + threadIdx.x;
    if (t >= G * 2) return;
    int g = t >> 1, c = t & 1;
    float acc = cb[c];
    for (int i = 0; i < HH; i++) acc = fmaf(g_pool[g * HH + i], cw[i * 2 + c], acc);
    for (int k = 0; k < 8; k++) acc = fmaf(clin[g * 8 + k], cw[(HH + k) * 2 + c], acc);
    out[t] = acc;
}

// ---------------- launch ----------------
extern "C" void kernel_launch(void* const* d_in, const int* in_sizes, int n_in,
                              void* d_out, int out_size)
{
    const float* x        = (const float*)d_in[0];
    const int*   ei       = (const int*)  d_in[1];
    const float* eattr    = (const float*)d_in[2];
    const int*   batch    = (const int*)  d_in[3];
    const float* clinical = (const float*)d_in[4];
    const float* lsw      = (const float*)d_in[5];
    const float* lsb      = (const float*)d_in[6];
    const float* ldw      = (const float*)d_in[7];
    const float* ldb      = (const float*)d_in[8];
    const float* ew       = (const float*)d_in[9];
    const float* eb       = (const float*)d_in[10];
    const float* t        = (const float*)d_in[11];
    const float* w1       = (const float*)d_in[12];
    const float* b1       = (const float*)d_in[13];
    const float* bng      = (const float*)d_in[14];
    const float* bnb      = (const float*)d_in[15];
    const float* bnm      = (const float*)d_in[16];
    const float* bnv      = (const float*)d_in[17];
    const float* w2       = (const float*)d_in[18];
    const float* b2       = (const float*)d_in[19];
    const float* ng       = (const float*)d_in[20];
    const float* nb       = (const float*)d_in[21];
    const float* nm       = (const float*)d_in[22];
    const float* nv       = (const float*)d_in[23];
    const float* cw       = (const float*)d_in[24];
    const float* cb       = (const float*)d_in[25];
    float* out = (float*)d_out;

    int N = in_sizes[0] / 256;
    int E = in_sizes[1] / 2;
    int G = in_sizes[4] / 8;

    float *p_xs, *p_xd, *p_o, *p_h, *p_r, *p_hmid;
    cudaGetSymbolAddress((void**)&p_xs, g_xs);
    cudaGetSymbolAddress((void**)&p_xd, g_xd);
    cudaGetSymbolAddress((void**)&p_o, g_o);
    cudaGetSymbolAddress((void**)&p_h, g_h);
    cudaGetSymbolAddress((void**)&p_r, g_r);
    cudaGetSymbolAddress((void**)&p_hmid, g_hmid);

    const int thr = 256;
    zero_k<<<(N + thr - 1) / thr, thr>>>(N);
    count_k<<<(E + thr - 1) / thr, thr>>>(ei, E);
    scan_k<<<1, 1024>>>(N);
    scatter_k<<<(E + thr - 1) / thr, thr>>>(ei, E);
    sortfill_k<<<(N + thr - 1) / thr, thr>>>(ei, eattr, N);

    int gmx = (N + 127) / 128;

    // input projections: xs0 = x@Wsrc+b, xd0 = x@Wdst+b
    sgemm<<<dim3(gmx, 1), thr>>>(x, lsw, lsb, p_xs, N, 256, 128,
        nullptr, nullptr, nullptr, nullptr, 0, nullptr,
        nullptr, nullptr, nullptr, nullptr, nullptr);
    sgemm<<<dim3(gmx, 1), thr>>>(x, ldw, ldb, p_xd, N, 256, 128,
        nullptr, nullptr, nullptr, nullptr, 0, nullptr,
        nullptr, nullptr, nullptr, nullptr, nullptr);

    for (int l = 0; l < LL; l++) {
        const float* xsl = l ? p_r : p_xs;
        const float* xdl = l ? p_r : p_xd;
        agg_kernel<<<(N + 7) / 8, thr>>>(xsl, xdl, p_o,
                                         ew + l * HH, eb + l * HH, t + l, N);
        // GEMM1: out @ W1 + b1 -> BN -> ReLU  => hmid [N, 256]
        sgemm<<<dim3(gmx, 2), thr>>>(p_o, w1 + (size_t)l * HH * H2, b1 + l * H2, p_hmid,
            N, HH, H2,
            bng + l * H2, bnb + l * H2, bnm + l * H2, bnv + l * H2, 1, nullptr,
            nullptr, nullptr, nullptr, nullptr, nullptr);
        // GEMM2: hmid @ W2 + b2 (+h residual for l>0) => h; also r = ReLU(BN_norm[(l+1)%4](h))
        int nl = (l + 1) & 3;
        sgemm<<<dim3(gmx, 1), thr>>>(p_hmid, w2 + (size_t)l * H2 * HH, b2 + l * HH, p_h,
            N, H2, HH,
            nullptr, nullptr, nullptr, nullptr, 0, l ? p_h : nullptr,
            p_r, ng + nl * HH, nb + nl * HH, nm + nl * HH, nv + nl * HH);
    }

    // after layer 3, p_r holds relu(bn(h, norm[0])) = hfin
    gstart_k<<<1, 128>>>(batch, N, G);
    pool_k<<<G, 128>>>(p_r);
    cls_k<<<1, 128>>>(clinical, cw, cb, out, G);
}